// round 14
// baseline (speedup 1.0000x reference)
#include <cuda_runtime.h>
#include <mma.h>
#include <math.h>
#include <stdint.h>
#include <cuda_fp16.h>

using namespace nvcuda;

#define NN      50000
#define NP      50048            // NN padded to multiple of 128
#define EE      800000
#define NFEAT   512
#define NHID    256
#define NCODE   64
#define NCLASS  40

// ---------------- device scratch (static, allocation-free) ----------------
__device__ __align__(16) __half g_xh  [(size_t)NN * NFEAT];     // fp16(x)
__device__ __align__(16) __half g_w1h [NFEAT * NHID];           // fp16(W1)
__device__ __align__(16) __half g_wmlh[NHID * 128];             // fp16([Wmu|Wlv])
__device__ __align__(16) __half g_wdech[NCODE * NHID];          // fp16(Wdec)
__device__ __align__(16) __half g_w2h [2 * NHID * 64];          // fp16(W2) padded cols
__device__ __align__(16) __half g_support1h[(size_t)NP * NHID]; // x @ W1 (fp16)
__device__ __align__(16) __half g_h1h[(size_t)NP * NHID];       // relu(spmm + b1) fp16
__device__ __align__(16) __half g_x1h[(size_t)NP * NHID];       // relu(z @ Wdec + bdec) fp16
__device__ __align__(16) __half g_support2h[(size_t)NP * 64];   // concat @ W2 fp16 (padded)
__device__ int   g_cnt   [NN];
__device__ int   g_rowptr[NN + 1];
__device__ int   g_cursor[NN];
__device__ int   g_esrc[EE];
__device__ float g_ew  [EE];

__device__ __forceinline__ unsigned h2u(__half2 h) {
    return *(unsigned*)&h;
}

__device__ __forceinline__ void cp_async16(void* smem, const void* gmem) {
    unsigned int s = (unsigned int)__cvta_generic_to_shared(smem);
    asm volatile("cp.async.cg.shared.global [%0], [%1], 16;" :: "r"(s), "l"(gmem));
}
__device__ __forceinline__ void cp_commit() {
    asm volatile("cp.async.commit_group;");
}
__device__ __forceinline__ void cp_wait1() {
    asm volatile("cp.async.wait_group 1;");
}
__device__ __forceinline__ void cp_wait0() {
    asm volatile("cp.async.wait_group 0;");
}

// ---------------- fp16 conversion kernels ----------------
__global__ void cvt_w_kernel(const float* __restrict__ W1,
                             const float* __restrict__ Wmu,
                             const float* __restrict__ Wlv,
                             const float* __restrict__ Wdec,
                             const float* __restrict__ W2) {
    int i = blockIdx.x * blockDim.x + threadIdx.x;
    if (i < NFEAT * NHID) g_w1h[i] = __float2half_rn(W1[i]);
    if (i < NHID * 128) {
        int k = i >> 7, j = i & 127;
        float v = (j < 64) ? Wmu[k * NCODE + j] : Wlv[k * NCODE + (j - 64)];
        g_wmlh[i] = __float2half_rn(v);
    }
    if (i < NCODE * NHID) g_wdech[i] = __float2half_rn(Wdec[i]);
    if (i < 2 * NHID * 64) {
        int k = i >> 6, j = i & 63;
        g_w2h[i] = __float2half_rn(j < NCLASS ? W2[k * NCLASS + j] : 0.0f);
    }
}

__global__ void cvt_x_kernel(const float* __restrict__ x) {
    size_t i = (size_t)blockIdx.x * blockDim.x + threadIdx.x;   // over NN*NFEAT/8
    if (i >= (size_t)NN * NFEAT / 8) return;
    const float4* p = (const float4*)x + i * 2;
    float4 a = p[0], b = p[1];
    uint4 u = make_uint4(h2u(__floats2half2_rn(a.x, a.y)), h2u(__floats2half2_rn(a.z, a.w)),
                         h2u(__floats2half2_rn(b.x, b.y)), h2u(__floats2half2_rn(b.z, b.w)));
    ((uint4*)g_xh)[i] = u;
}

// ---------------- CSR build ----------------
__global__ void hist_kernel(const int* __restrict__ dst) {
    int e = blockIdx.x * blockDim.x + threadIdx.x;
    if (e < EE) atomicAdd(&g_cnt[dst[e]], 1);
}

__global__ __launch_bounds__(1024) void scan_kernel() {
    __shared__ int sums[1024];
    const int T = 1024;
    const int IT = (NN + T - 1) / T;
    int t = threadIdx.x;
    int base = t * IT;
    int s = 0;
    for (int i = 0; i < IT; i++) {
        int idx = base + i;
        if (idx < NN) s += g_cnt[idx];
    }
    sums[t] = s;
    __syncthreads();
    for (int off = 1; off < T; off <<= 1) {
        int v = (t >= off) ? sums[t - off] : 0;
        __syncthreads();
        sums[t] += v;
        __syncthreads();
    }
    int run = sums[t] - s;
    for (int i = 0; i < IT; i++) {
        int idx = base + i;
        if (idx < NN) {
            g_rowptr[idx] = run;
            g_cursor[idx] = run;
            run += g_cnt[idx];
        }
    }
    if (t == T - 1) g_rowptr[NN] = sums[T - 1];
}

__global__ void scatter_kernel(const int* __restrict__ src,
                               const int* __restrict__ dst,
                               const float* __restrict__ w) {
    int e = blockIdx.x * blockDim.x + threadIdx.x;
    if (e < EE) {
        int d = dst[e];
        int p = atomicAdd(&g_cursor[d], 1);
        g_esrc[p] = src[e];
        g_ew[p]   = w[e];
    }
}

// =========================================================================
// GEMM1 (fp16 HMMA, cp.async double-buffered): g_support1h = fp16(x @ W1)
// M=NP, K=512, N=256. BM=128, BN=128, BK=32, 8 warps (2x4), warp 64x32.
// =========================================================================
__global__ __launch_bounds__(256) void gemm1_tc() {
    __shared__ __half As[2][128][40];
    __shared__ __half Bs[2][32][136];
    const int t   = threadIdx.x;
    const int wid = t >> 5;
    const int wr  = wid >> 2;     // 0..1
    const int wc  = wid & 3;      // 0..3
    const int row0 = blockIdx.y * 128;
    const int col0 = blockIdx.x * 128;

    wmma::fragment<wmma::accumulator, 16, 16, 16, float> acc[4][2];
#pragma unroll
    for (int i = 0; i < 4; i++)
#pragma unroll
        for (int j = 0; j < 2; j++) wmma::fill_fragment(acc[i][j], 0.0f);

    const int arow = t >> 1;          // 0..127
    const int ac16 = (t & 1) * 16;    // 0/16
    const int brow = t >> 3;          // 0..31
    const int bc16 = (t & 7) * 16;    // 0..112
    int garow = row0 + arow; if (garow >= NN) garow = NN - 1;
    const __half* Ap = g_xh + (size_t)garow * NFEAT;
    const __half* Bp = g_w1h + col0 + bc16;

    const int NIT = NFEAT / 32;   // 16
    cp_async16(&As[0][arow][ac16],     Ap + ac16);
    cp_async16(&As[0][arow][ac16 + 8], Ap + ac16 + 8);
    cp_async16(&Bs[0][brow][bc16],     Bp + (size_t)brow * NHID);
    cp_async16(&Bs[0][brow][bc16 + 8], Bp + (size_t)brow * NHID + 8);
    cp_commit();

    for (int i = 0; i < NIT; i++) {
        if (i + 1 < NIT) {
            int k1 = (i + 1) * 32;
            int nb = (i + 1) & 1;
            cp_async16(&As[nb][arow][ac16],     Ap + k1 + ac16);
            cp_async16(&As[nb][arow][ac16 + 8], Ap + k1 + ac16 + 8);
            cp_async16(&Bs[nb][brow][bc16],     Bp + (size_t)(k1 + brow) * NHID);
            cp_async16(&Bs[nb][brow][bc16 + 8], Bp + (size_t)(k1 + brow) * NHID + 8);
            cp_commit();
            cp_wait1();
        } else {
            cp_wait0();
        }
        __syncthreads();
        int cb = i & 1;
#pragma unroll
        for (int kk = 0; kk < 32; kk += 16) {
            wmma::fragment<wmma::matrix_a, 16, 16, 16, __half, wmma::row_major> af[4];
            wmma::fragment<wmma::matrix_b, 16, 16, 16, __half, wmma::row_major> bf[2];
#pragma unroll
            for (int ii = 0; ii < 4; ii++)
                wmma::load_matrix_sync(af[ii], &As[cb][wr * 64 + ii * 16][kk], 40);
#pragma unroll
            for (int j = 0; j < 2; j++)
                wmma::load_matrix_sync(bf[j], &Bs[cb][kk][wc * 32 + j * 16], 136);
#pragma unroll
            for (int ii = 0; ii < 4; ii++)
#pragma unroll
                for (int j = 0; j < 2; j++)
                    wmma::mma_sync(acc[ii][j], af[ii], bf[j], acc[ii][j]);
        }
        __syncthreads();
    }

    float* stage = (float*)&As[0][0][0] + wid * 320;
    const int L = t & 31;
    const int rr = L >> 1;
    const int cc = (L & 1) * 8;
#pragma unroll
    for (int i = 0; i < 4; i++)
#pragma unroll
        for (int j = 0; j < 2; j++) {
            wmma::store_matrix_sync(stage, acc[i][j], 20, wmma::mem_row_major);
            __syncwarp();
            const float* sp = stage + rr * 20 + cc;
            __half2 h0 = __floats2half2_rn(sp[0], sp[1]);
            __half2 h1 = __floats2half2_rn(sp[2], sp[3]);
            __half2 h2 = __floats2half2_rn(sp[4], sp[5]);
            __half2 h3 = __floats2half2_rn(sp[6], sp[7]);
            int gr = row0 + wr * 64 + i * 16 + rr;
            int gc = col0 + wc * 32 + j * 16 + cc;
            *(uint4*)(g_support1h + (size_t)gr * NHID + gc) =
                make_uint4(h2u(h0), h2u(h1), h2u(h2), h2u(h3));
            __syncwarp();
        }
}

// =========================================================================
// zdec fused: phase1 tmp = h1 @ [Wmu|Wlv] (regs);
// phase z: z = (mu+bmu) + eps*exp(lv+blv) via smem exchange (fp16 tile);
// phase2: x1 = relu(z @ Wdec + bdec) -> g_x1h.
// =========================================================================
__global__ __launch_bounds__(256) void zdec_tc(const float* __restrict__ bmu,
                                               const float* __restrict__ blv,
                                               const float* __restrict__ eps,
                                               const float* __restrict__ bdec) {
    extern __shared__ char arena[];
    __half (*hA)[128][40]  = (__half (*)[128][40])arena;            // 20480 B
    __half (*hB)[32][136]  = (__half (*)[32][136])(arena + 20480);  // 17408 B
    float*  lv_s  = (float*)arena;                   // [128][68]  34816 B
    __half* z_s   = (__half*)(arena + 34816);        // [128][72]  18432 B
    float*  stg   = (float*)(arena + 53248);         // 8 * 320 floats
    __half* bB    = (__half*)arena;                  // [64][136]  17408 B (phase2)

    const int t   = threadIdx.x;
    const int wid = t >> 5;
    const int wr  = wid >> 2;     // 0..1
    const int wc  = wid & 3;      // 0..3
    const int row0 = blockIdx.x * 128;
    const int L  = t & 31;
    const int rr = L >> 1;
    const int cc = (L & 1) * 8;

    wmma::fragment<wmma::accumulator, 16, 16, 16, float> acc[4][2];
#pragma unroll
    for (int i = 0; i < 4; i++)
#pragma unroll
        for (int j = 0; j < 2; j++) wmma::fill_fragment(acc[i][j], 0.0f);

    // ---- phase 1: tmp = h1 @ [Wmu|Wlv], K=256, N=128 ----
    {
        const int arow = t >> 1;
        const int ac16 = (t & 1) * 16;
        const int brow = t >> 3;
        const int bc16 = (t & 7) * 16;
        int garow = row0 + arow; if (garow >= NN) garow = NN - 1;
        const __half* Ap = g_h1h + (size_t)garow * NHID;
        const __half* Bp = g_wmlh + bc16;

        const int NIT = NHID / 32;   // 8
        cp_async16(&hA[0][arow][ac16],     Ap + ac16);
        cp_async16(&hA[0][arow][ac16 + 8], Ap + ac16 + 8);
        cp_async16(&hB[0][brow][bc16],     Bp + (size_t)brow * 128);
        cp_async16(&hB[0][brow][bc16 + 8], Bp + (size_t)brow * 128 + 8);
        cp_commit();

        for (int i = 0; i < NIT; i++) {
            if (i + 1 < NIT) {
                int k1 = (i + 1) * 32;
                int nb = (i + 1) & 1;
                cp_async16(&hA[nb][arow][ac16],     Ap + k1 + ac16);
                cp_async16(&hA[nb][arow][ac16 + 8], Ap + k1 + ac16 + 8);
                cp_async16(&hB[nb][brow][bc16],     Bp + (size_t)(k1 + brow) * 128);
                cp_async16(&hB[nb][brow][bc16 + 8], Bp + (size_t)(k1 + brow) * 128 + 8);
                cp_commit();
                cp_wait1();
            } else {
                cp_wait0();
            }
            __syncthreads();
            int cb = i & 1;
#pragma unroll
            for (int kk = 0; kk < 32; kk += 16) {
                wmma::fragment<wmma::matrix_a, 16, 16, 16, __half, wmma::row_major> af[4];
                wmma::fragment<wmma::matrix_b, 16, 16, 16, __half, wmma::row_major> bf[2];
#pragma unroll
                for (int ii = 0; ii < 4; ii++)
                    wmma::load_matrix_sync(af[ii], &hA[cb][wr * 64 + ii * 16][kk], 40);
#pragma unroll
                for (int j = 0; j < 2; j++)
                    wmma::load_matrix_sync(bf[j], &hB[cb][kk][wc * 32 + j * 16], 136);
#pragma unroll
                for (int ii = 0; ii < 4; ii++)
#pragma unroll
                    for (int j = 0; j < 2; j++)
                        wmma::mma_sync(acc[ii][j], af[ii], bf[j], acc[ii][j]);
            }
            __syncthreads();
        }
    }

    // ---- phase z ----
    if (wc >= 2) {
#pragma unroll
        for (int i = 0; i < 4; i++)
#pragma unroll
            for (int j = 0; j < 2; j++)
                wmma::store_matrix_sync(lv_s + (wr * 64 + i * 16) * 68 + (wc - 2) * 32 + j * 16,
                                        acc[i][j], 68, wmma::mem_row_major);
    }
    __syncthreads();
    if (wc < 2) {
        float* stage = stg + wid * 320;
#pragma unroll
        for (int i = 0; i < 4; i++)
#pragma unroll
            for (int j = 0; j < 2; j++) {
                wmma::store_matrix_sync(stage, acc[i][j], 20, wmma::mem_row_major);
                __syncwarp();
                const float* sp = stage + rr * 20 + cc;
                int row = wr * 64 + i * 16 + rr;
                int col = wc * 32 + j * 16 + cc;
                int ge = row0 + row; if (ge >= NN) ge = NN - 1;
                float4 e0 = *(const float4*)(eps + (size_t)ge * NCODE + col);
                float4 e1 = *(const float4*)(eps + (size_t)ge * NCODE + col + 4);
                float4 l0 = *(const float4*)(lv_s + row * 68 + col);
                float4 l1 = *(const float4*)(lv_s + row * 68 + col + 4);
                float4 bm0 = *(const float4*)(bmu + col);
                float4 bm1 = *(const float4*)(bmu + col + 4);
                float4 bl0 = *(const float4*)(blv + col);
                float4 bl1 = *(const float4*)(blv + col + 4);
                float z0 = (sp[0] + bm0.x) + e0.x * expf(l0.x + bl0.x);
                float z1 = (sp[1] + bm0.y) + e0.y * expf(l0.y + bl0.y);
                float z2 = (sp[2] + bm0.z) + e0.z * expf(l0.z + bl0.z);
                float z3 = (sp[3] + bm0.w) + e0.w * expf(l0.w + bl0.w);
                float z4 = (sp[4] + bm1.x) + e1.x * expf(l1.x + bl1.x);
                float z5 = (sp[5] + bm1.y) + e1.y * expf(l1.y + bl1.y);
                float z6 = (sp[6] + bm1.z) + e1.z * expf(l1.z + bl1.z);
                float z7 = (sp[7] + bm1.w) + e1.w * expf(l1.w + bl1.w);
                *(uint4*)(z_s + row * 72 + col) =
                    make_uint4(h2u(__floats2half2_rn(z0, z1)), h2u(__floats2half2_rn(z2, z3)),
                               h2u(__floats2half2_rn(z4, z5)), h2u(__floats2half2_rn(z6, z7)));
                __syncwarp();
            }
    }
    __syncthreads();

    // ---- phase 2: x1 = relu(z @ Wdec + bdec), K=64, N=256 in two halves ----
    for (int col0 = 0; col0 < NHID; col0 += 128) {
        {
            const __half* wp = g_wdech + (size_t)(t >> 2) * NHID + col0 + (t & 3) * 32;
            __half* bp = bB + (t >> 2) * 136 + (t & 3) * 32;
            *(uint4*)(bp)      = *(const uint4*)(wp);
            *(uint4*)(bp + 8)  = *(const uint4*)(wp + 8);
            *(uint4*)(bp + 16) = *(const uint4*)(wp + 16);
            *(uint4*)(bp + 24) = *(const uint4*)(wp + 24);
        }
        __syncthreads();

        wmma::fragment<wmma::accumulator, 16, 16, 16, float> acc2[4][2];
#pragma unroll
        for (int i = 0; i < 4; i++)
#pragma unroll
            for (int j = 0; j < 2; j++) wmma::fill_fragment(acc2[i][j], 0.0f);

#pragma unroll
        for (int kk = 0; kk < NCODE; kk += 16) {
            wmma::fragment<wmma::matrix_a, 16, 16, 16, __half, wmma::row_major> af[4];
            wmma::fragment<wmma::matrix_b, 16, 16, 16, __half, wmma::row_major> bf[2];
#pragma unroll
            for (int i = 0; i < 4; i++)
                wmma::load_matrix_sync(af[i], z_s + (wr * 64 + i * 16) * 72 + kk, 72);
#pragma unroll
            for (int j = 0; j < 2; j++)
                wmma::load_matrix_sync(bf[j], bB + kk * 136 + wc * 32 + j * 16, 136);
#pragma unroll
            for (int i = 0; i < 4; i++)
#pragma unroll
                for (int j = 0; j < 2; j++)
                    wmma::mma_sync(acc2[i][j], af[i], bf[j], acc2[i][j]);
        }

        float* stage = stg + wid * 320;
#pragma unroll
        for (int i = 0; i < 4; i++)
#pragma unroll
            for (int j = 0; j < 2; j++) {
                wmma::store_matrix_sync(stage, acc2[i][j], 20, wmma::mem_row_major);
                __syncwarp();
                const float* sp = stage + rr * 20 + cc;
                int gr = row0 + wr * 64 + i * 16 + rr;
                int gc = col0 + wc * 32 + j * 16 + cc;
                float4 bd0 = *(const float4*)(bdec + gc);
                float4 bd1 = *(const float4*)(bdec + gc + 4);
                float v0 = fmaxf(sp[0] + bd0.x, 0.f), v1 = fmaxf(sp[1] + bd0.y, 0.f);
                float v2 = fmaxf(sp[2] + bd0.z, 0.f), v3 = fmaxf(sp[3] + bd0.w, 0.f);
                float v4 = fmaxf(sp[4] + bd1.x, 0.f), v5 = fmaxf(sp[5] + bd1.y, 0.f);
                float v6 = fmaxf(sp[6] + bd1.z, 0.f), v7 = fmaxf(sp[7] + bd1.w, 0.f);
                *(uint4*)(g_x1h + (size_t)gr * NHID + gc) =
                    make_uint4(h2u(__floats2half2_rn(v0, v1)), h2u(__floats2half2_rn(v2, v3)),
                               h2u(__floats2half2_rn(v4, v5)), h2u(__floats2half2_rn(v6, v7)));
                __syncwarp();
            }
        __syncthreads();
    }
}

// =========================================================================
// out_h1: g_support2h = h1 @ W2[NHID:2*NHID]   (partial; overlaps zdec)
// M=NP, K=256, N=64. cp.async double-buffered.
// =========================================================================
__global__ __launch_bounds__(256) void out_h1_tc() {
    __shared__ __half As[2][128][40];
    __shared__ __half Bs[2][32][72];
    const int t   = threadIdx.x;
    const int wid = t >> 5;
    const int wr  = wid >> 1;     // 0..3
    const int wc  = wid & 1;      // 0..1
    const int row0 = blockIdx.x * 128;

    wmma::fragment<wmma::accumulator, 16, 16, 16, float> acc[2][2];
#pragma unroll
    for (int i = 0; i < 2; i++)
#pragma unroll
        for (int j = 0; j < 2; j++) wmma::fill_fragment(acc[i][j], 0.0f);

    const int arow = t >> 1;
    const int ac16 = (t & 1) * 16;
    const int brow = t >> 3;
    const int bc8  = (t & 7) * 8;
    int garow = row0 + arow; if (garow >= NN) garow = NN - 1;
    const __half* Ap = g_h1h + (size_t)garow * NHID;
    const __half* Bbase = g_w2h + (size_t)NHID * 64;   // bottom half of W2

    const int NIT = NHID / 32;   // 8
    cp_async16(&As[0][arow][ac16],     Ap + ac16);
    cp_async16(&As[0][arow][ac16 + 8], Ap + ac16 + 8);
    cp_async16(&Bs[0][brow][bc8], Bbase + (size_t)brow * 64 + bc8);
    cp_commit();

    for (int i = 0; i < NIT; i++) {
        if (i + 1 < NIT) {
            int k1 = (i + 1) * 32;
            int nb = (i + 1) & 1;
            cp_async16(&As[nb][arow][ac16],     Ap + k1 + ac16);
            cp_async16(&As[nb][arow][ac16 + 8], Ap + k1 + ac16 + 8);
            cp_async16(&Bs[nb][brow][bc8], Bbase + (size_t)(k1 + brow) * 64 + bc8);
            cp_commit();
            cp_wait1();
        } else {
            cp_wait0();
        }
        __syncthreads();
        int cb = i & 1;
#pragma unroll
        for (int kk = 0; kk < 32; kk += 16) {
            wmma::fragment<wmma::matrix_a, 16, 16, 16, __half, wmma::row_major> af[2];
            wmma::fragment<wmma::matrix_b, 16, 16, 16, __half, wmma::row_major> bf[2];
#pragma unroll
            for (int ii = 0; ii < 2; ii++)
                wmma::load_matrix_sync(af[ii], &As[cb][wr * 32 + ii * 16][kk], 40);
#pragma unroll
            for (int j = 0; j < 2; j++)
                wmma::load_matrix_sync(bf[j], &Bs[cb][kk][wc * 32 + j * 16], 72);
#pragma unroll
            for (int ii = 0; ii < 2; ii++)
#pragma unroll
                for (int j = 0; j < 2; j++)
                    wmma::mma_sync(acc[ii][j], af[ii], bf[j], acc[ii][j]);
        }
        __syncthreads();
    }

    float* stage = (float*)&As[0][0][0] + wid * 320;
    const int L = t & 31;
    const int rr = L >> 1;
    const int cc = (L & 1) * 8;
#pragma unroll
    for (int i = 0; i < 2; i++)
#pragma unroll
        for (int j = 0; j < 2; j++) {
            wmma::store_matrix_sync(stage, acc[i][j], 20, wmma::mem_row_major);
            __syncwarp();
            const float* sp = stage + rr * 20 + cc;
            int r = row0 + wr * 32 + i * 16 + rr;
            int c = wc * 32 + j * 16 + cc;
            *(uint4*)(g_support2h + (size_t)r * 64 + c) =
                make_uint4(h2u(__floats2half2_rn(sp[0], sp[1])),
                           h2u(__floats2half2_rn(sp[2], sp[3])),
                           h2u(__floats2half2_rn(sp[4], sp[5])),
                           h2u(__floats2half2_rn(sp[6], sp[7])));
            __syncwarp();
        }
}

// =========================================================================
// out_x1: g_support2h += x1 @ W2[0:NHID]   (reads partial, writes final)
// M=NP, K=256, N=64.
// =========================================================================
__global__ __launch_bounds__(256) void out_x1_tc() {
    __shared__ __half As[2][128][40];
    __shared__ __half Bs[2][32][72];
    const int t   = threadIdx.x;
    const int wid = t >> 5;
    const int wr  = wid >> 1;
    const int wc  = wid & 1;
    const int row0 = blockIdx.x * 128;

    wmma::fragment<wmma::accumulator, 16, 16, 16, float> acc[2][2];
#pragma unroll
    for (int i = 0; i < 2; i++)
#pragma unroll
        for (int j = 0; j < 2; j++) wmma::fill_fragment(acc[i][j], 0.0f);

    const int arow = t >> 1;
    const int ac16 = (t & 1) * 16;
    const int brow = t >> 3;
    const int bc8  = (t & 7) * 8;
    int garow = row0 + arow; if (garow >= NN) garow = NN - 1;
    const __half* Ap = g_x1h + (size_t)garow * NHID;

    const int NIT = NHID / 32;   // 8
    cp_async16(&As[0][arow][ac16],     Ap + ac16);
    cp_async16(&As[0][arow][ac16 + 8], Ap + ac16 + 8);
    cp_async16(&Bs[0][brow][bc8], g_w2h + (size_t)brow * 64 + bc8);
    cp_commit();

    for (int i = 0; i < NIT; i++) {
        if (i + 1 < NIT) {
            int k1 = (i + 1) * 32;
            int nb = (i + 1) & 1;
            cp_async16(&As[nb][arow][ac16],     Ap + k1 + ac16);
            cp_async16(&As[nb][arow][ac16 + 8], Ap + k1 + ac16 + 8);
            cp_async16(&Bs[nb][brow][bc8], g_w2h + (size_t)(k1 + brow) * 64 + bc8);
            cp_commit();
            cp_wait1();
        } else {
            cp_wait0();
        }
        __syncthreads();
        int cb = i & 1;
#pragma unroll
        for (int kk = 0; kk < 32; kk += 16) {
            wmma::fragment<wmma::matrix_a, 16, 16, 16, __half, wmma::row_major> af[2];
            wmma::fragment<wmma::matrix_b, 16, 16, 16, __half, wmma::row_major> bf[2];
#pragma unroll
            for (int ii = 0; ii < 2; ii++)
                wmma::load_matrix_sync(af[ii], &As[cb][wr * 32 + ii * 16][kk], 40);
#pragma unroll
            for (int j = 0; j < 2; j++)
                wmma::load_matrix_sync(bf[j], &Bs[cb][kk][wc * 32 + j * 16], 72);
#pragma unroll
            for (int ii = 0; ii < 2; ii++)
#pragma unroll
                for (int j = 0; j < 2; j++)
                    wmma::mma_sync(acc[ii][j], af[ii], bf[j], acc[ii][j]);
        }
        __syncthreads();
    }

    // epilogue: add fp16 partial (h1 half) and store final
    float* stage = (float*)&As[0][0][0] + wid * 320;
    const int L = t & 31;
    const int rr = L >> 1;
    const int cc = (L & 1) * 8;
#pragma unroll
    for (int i = 0; i < 2; i++)
#pragma unroll
        for (int j = 0; j < 2; j++) {
            wmma::store_matrix_sync(stage, acc[i][j], 20, wmma::mem_row_major);
            __syncwarp();
            const float* sp = stage + rr * 20 + cc;
            int r = row0 + wr * 32 + i * 16 + rr;
            int c = wc * 32 + j * 16 + cc;
            uint4 pu = *(uint4*)(g_support2h + (size_t)r * 64 + c);
            __half2* ph = (__half2*)&pu;
            float2 p0 = __half22float2(ph[0]);
            float2 p1 = __half22float2(ph[1]);
            float2 p2 = __half22float2(ph[2]);
            float2 p3 = __half22float2(ph[3]);
            *(uint4*)(g_support2h + (size_t)r * 64 + c) =
                make_uint4(h2u(__floats2half2_rn(sp[0] + p0.x, sp[1] + p0.y)),
                           h2u(__floats2half2_rn(sp[2] + p1.x, sp[3] + p1.y)),
                           h2u(__floats2half2_rn(sp[4] + p2.x, sp[5] + p2.y)),
                           h2u(__floats2half2_rn(sp[6] + p3.x, sp[7] + p3.y)));
            __syncwarp();
        }
}

// ---------------- spmm1 + bias + relu (fp16 gather, 8x unrolled) ---------
__global__ void spmm_relu_kernel(const float* __restrict__ b1) {
    int warp = (blockIdx.x * blockDim.x + threadIdx.x) >> 5;
    int lane = threadIdx.x & 31;
    if (warp >= NN) return;
    int beg = g_rowptr[warp];
    int end = g_rowptr[warp + 1];
    float acc[8] = {0, 0, 0, 0, 0, 0, 0, 0};
    const int co = lane * 8;
    int e = beg;
    for (; e + 8 <= end; e += 8) {
        uint4 u[8];
        float w[8];
#pragma unroll
        for (int k = 0; k < 8; k++) {
            int s = g_esrc[e + k];
            w[k] = g_ew[e + k];
            u[k] = *(const uint4*)(g_support1h + (size_t)s * NHID + co);
        }
#pragma unroll
        for (int k = 0; k < 8; k++) {
            __half2* h = (__half2*)&u[k];
#pragma unroll
            for (int q = 0; q < 4; q++) {
                float2 f = __half22float2(h[q]);
                acc[2 * q]     += w[k] * f.x;
                acc[2 * q + 1] += w[k] * f.y;
            }
        }
    }
    for (; e < end; e++) {
        int s = g_esrc[e];
        float w = g_ew[e];
        uint4 u = *(const uint4*)(g_support1h + (size_t)s * NHID + co);
        __half2* h = (__half2*)&u;
#pragma unroll
        for (int q = 0; q < 4; q++) {
            float2 f = __half22float2(h[q]);
            acc[2 * q]     += w * f.x;
            acc[2 * q + 1] += w * f.y;
        }
    }
    float4 bb0 = *(const float4*)(b1 + co);
    float4 bb1 = *(const float4*)(b1 + co + 4);
    float o[8];
    o[0] = fmaxf(acc[0] + bb0.x, 0.f); o[1] = fmaxf(acc[1] + bb0.y, 0.f);
    o[2] = fmaxf(acc[2] + bb0.z, 0.f); o[3] = fmaxf(acc[3] + bb0.w, 0.f);
    o[4] = fmaxf(acc[4] + bb1.x, 0.f); o[5] = fmaxf(acc[5] + bb1.y, 0.f);
    o[6] = fmaxf(acc[6] + bb1.z, 0.f); o[7] = fmaxf(acc[7] + bb1.w, 0.f);
    uint4 u = make_uint4(h2u(__floats2half2_rn(o[0], o[1])),
                         h2u(__floats2half2_rn(o[2], o[3])),
                         h2u(__floats2half2_rn(o[4], o[5])),
                         h2u(__floats2half2_rn(o[6], o[7])));
    *(uint4*)(g_h1h + (size_t)warp * NHID + co) = u;
}

// ---------------- spmm2 (fp16 gather, 4x unrolled) + log_softmax ---------
__global__ void spmm_softmax_kernel(const float* __restrict__ b2,
                                    float* __restrict__ out) {
    int warp = (blockIdx.x * blockDim.x + threadIdx.x) >> 5;
    int lane = threadIdx.x & 31;
    if (warp >= NN) return;
    int beg = g_rowptr[warp];
    int end = g_rowptr[warp + 1];
    bool active = lane < 10;                   // 10 lanes x 4 cols = 40
    float acc[4] = {0, 0, 0, 0};
    int e = beg;
    for (; e + 4 <= end; e += 4) {
        if (active) {
            uint2 u[4];
            float w[4];
#pragma unroll
            for (int k = 0; k < 4; k++) {
                int s = g_esrc[e + k];
                w[k] = g_ew[e + k];
                u[k] = *(const uint2*)(g_support2h + (size_t)s * 64 + lane * 4);
            }
#pragma unroll
            for (int k = 0; k < 4; k++) {
                __half2* hp = (__half2*)&u[k];
                float2 f0 = __half22float2(hp[0]);
                float2 f1 = __half22float2(hp[1]);
                acc[0] += w[k] * f0.x; acc[1] += w[k] * f0.y;
                acc[2] += w[k] * f1.x; acc[3] += w[k] * f1.y;
            }
        }
    }
    for (; e < end; e++) {
        int s = g_esrc[e];
        float w = g_ew[e];
        if (active) {
            uint2 u = *(const uint2*)(g_support2h + (size_t)s * 64 + lane * 4);
            __half2* hp = (__half2*)&u;
            float2 f0 = __half22float2(hp[0]);
            float2 f1 = __half22float2(hp[1]);
            acc[0] += w * f0.x; acc[1] += w * f0.y;
            acc[2] += w * f1.x; acc[3] += w * f1.y;
        }
    }
    float4 v = make_float4(-INFINITY, -INFINITY, -INFINITY, -INFINITY);
    if (active) {
        float4 b = *(const float4*)(b2 + lane * 4);
        v.x = acc[0] + b.x; v.y = acc[1] + b.y; v.z = acc[2] + b.z; v.w = acc[3] + b.w;
    }
    float m = fmaxf(fmaxf(v.x, v.y), fmaxf(v.z, v.w));
#pragma unroll
    for (int off = 16; off > 0; off >>= 1)
        m = fmaxf(m, __shfl_xor_sync(0xFFFFFFFFu, m, off));
    float s = active ? (expf(v.x - m) + expf(v.y - m) + expf(v.z - m) + expf(v.w - m)) : 0.0f;
#pragma unroll
    for (int off = 16; off > 0; off >>= 1)
        s += __shfl_xor_sync(0xFFFFFFFFu, s, off);
    float lse = m + logf(s);
    if (active) {
        float4 o;
        o.x = v.x - lse; o.y = v.y - lse; o.z = v.z - lse; o.w = v.w - lse;
        ((float4*)(out + (size_t)warp * NCLASS))[lane] = o;
    }
}

// ---------------- launch ----------------
extern "C" void kernel_launch(void* const* d_in, const int* in_sizes, int n_in,
                              void* d_out, int out_size) {
    const float* x        = (const float*)d_in[0];
    const int*   edge_src = (const int*)  d_in[1];
    const int*   edge_dst = (const int*)  d_in[2];
    const float* edge_w   = (const float*)d_in[3];
    const float* eps      = (const float*)d_in[4];
    const float* W1       = (const float*)d_in[5];
    const float* b1       = (const float*)d_in[6];
    const float* W_mu     = (const float*)d_in[7];
    const float* b_mu     = (const float*)d_in[8];
    const float* W_lv     = (const float*)d_in[9];
    const float* b_lv     = (const float*)d_in[10];
    const float* W_dec    = (const float*)d_in[11];
    const float* b_dec    = (const float*)d_in[12];
    const float* W2       = (const float*)d_in[13];
    const float* b2       = (const float*)d_in[14];
    float* out = (float*)d_out;

    static cudaStream_t s2 = nullptr;
    static cudaEvent_t ev_fork = nullptr, ev_join = nullptr;
    static cudaEvent_t ev_h1 = nullptr, ev_out = nullptr;
    static bool init_done = false;
    if (!init_done) {
        cudaFuncSetAttribute(zdec_tc, cudaFuncAttributeMaxDynamicSharedMemorySize, 65536);
        cudaStreamCreateWithFlags(&s2, cudaStreamNonBlocking);
        cudaEventCreateWithFlags(&ev_fork, cudaEventDisableTiming);
        cudaEventCreateWithFlags(&ev_join, cudaEventDisableTiming);
        cudaEventCreateWithFlags(&ev_h1, cudaEventDisableTiming);
        cudaEventCreateWithFlags(&ev_out, cudaEventDisableTiming);
        init_done = true;
    }

    void* cnt_ptr = nullptr;
    cudaGetSymbolAddress(&cnt_ptr, g_cnt);

    // fork: CSR chain on s2, concurrent with cvt + gemm1 on the main stream
    cudaEventRecord(ev_fork, 0);
    cudaStreamWaitEvent(s2, ev_fork, 0);

    cudaMemsetAsync(cnt_ptr, 0, NN * sizeof(int), s2);
    hist_kernel<<<(EE + 255) / 256, 256, 0, s2>>>(edge_dst);
    scan_kernel<<<1, 1024, 0, s2>>>();
    scatter_kernel<<<(EE + 255) / 256, 256, 0, s2>>>(edge_src, edge_dst, edge_w);
    cudaEventRecord(ev_join, s2);

    cvt_w_kernel<<<(NFEAT * NHID + 255) / 256, 256>>>(W1, W_mu, W_lv, W_dec, W2);
    cvt_x_kernel<<<((size_t)NN * NFEAT / 8 + 255) / 256, 256>>>(x);
    gemm1_tc<<<dim3(NHID / 128, NP / 128), 256>>>();

    // join CSR
    cudaStreamWaitEvent(0, ev_join, 0);

    // h1(fp16) = relu(spmm + b1)
    spmm_relu_kernel<<<(NN * 32 + 255) / 256, 256>>>(b1);

    // fork 2: out_h1 (needs h1 only) overlaps zdec
    cudaEventRecord(ev_h1, 0);
    cudaStreamWaitEvent(s2, ev_h1, 0);
    out_h1_tc<<<NP / 128, 256, 0, s2>>>();
    cudaEventRecord(ev_out, s2);

    // fused: tmp -> z -> x1 (main)
    zdec_tc<<<NP / 128, 256, 65536>>>(b_mu, b_lv, eps, b_dec);

    // join 2, then final out half and softmax
    cudaStreamWaitEvent(0, ev_out, 0);
    out_x1_tc<<<NP / 128, 256>>>();
    spmm_softmax_kernel<<<(NN * 32 + 255) / 256, 256>>>(b2, out);
}

// round 15
// speedup vs baseline: 1.4447x; 1.4447x over previous
#include <cuda_runtime.h>
#include <mma.h>
#include <math.h>
#include <stdint.h>
#include <cuda_fp16.h>

using namespace nvcuda;

#define NN      50000
#define NP      50048            // NN padded to multiple of 128
#define EE      800000
#define NFEAT   512
#define NHID    256
#define NCODE   64
#define NCLASS  40

// ---------------- device scratch (static, allocation-free) ----------------
__device__ __align__(16) __half g_xh  [(size_t)NN * NFEAT];     // fp16(x)
__device__ __align__(16) __half g_w1h [NFEAT * NHID];           // fp16(W1)
__device__ __align__(16) __half g_wmlh[NHID * 128];             // fp16([Wmu|Wlv])
__device__ __align__(16) __half g_wdech[NCODE * NHID];          // fp16(Wdec)
__device__ __align__(16) __half g_w2h [2 * NHID * 64];          // fp16(W2) padded cols
__device__ __align__(16) __half g_support1h[(size_t)NP * NHID]; // x @ W1 (fp16)
__device__ __align__(16) __half g_h1h[(size_t)NP * NHID];       // relu(spmm + b1) fp16
__device__ __align__(16) __half g_x1h[(size_t)NP * NHID];       // relu(z @ Wdec + bdec) fp16
__device__ __align__(16) __half g_support2h[(size_t)NP * 64];   // concat @ W2 fp16 (padded)
__device__ int   g_cnt   [NN];
__device__ int   g_rowptr[NN + 1];
__device__ int   g_cursor[NN];
__device__ int   g_esrc[EE];
__device__ float g_ew  [EE];

__device__ __forceinline__ unsigned h2u(__half2 h) {
    return *(unsigned*)&h;
}

__device__ __forceinline__ void cp_async16(void* smem, const void* gmem) {
    unsigned int s = (unsigned int)__cvta_generic_to_shared(smem);
    asm volatile("cp.async.cg.shared.global [%0], [%1], 16;" :: "r"(s), "l"(gmem));
}
__device__ __forceinline__ void cp_commit() {
    asm volatile("cp.async.commit_group;");
}
__device__ __forceinline__ void cp_wait1() {
    asm volatile("cp.async.wait_group 1;");
}
__device__ __forceinline__ void cp_wait0() {
    asm volatile("cp.async.wait_group 0;");
}

// ---------------- fp16 conversion kernels ----------------
__global__ void cvt_w_kernel(const float* __restrict__ W1,
                             const float* __restrict__ Wmu,
                             const float* __restrict__ Wlv,
                             const float* __restrict__ Wdec,
                             const float* __restrict__ W2) {
    int i = blockIdx.x * blockDim.x + threadIdx.x;
    if (i < NFEAT * NHID) g_w1h[i] = __float2half_rn(W1[i]);
    if (i < NHID * 128) {
        int k = i >> 7, j = i & 127;
        float v = (j < 64) ? Wmu[k * NCODE + j] : Wlv[k * NCODE + (j - 64)];
        g_wmlh[i] = __float2half_rn(v);
    }
    if (i < NCODE * NHID) g_wdech[i] = __float2half_rn(Wdec[i]);
    if (i < 2 * NHID * 64) {
        int k = i >> 6, j = i & 63;
        g_w2h[i] = __float2half_rn(j < NCLASS ? W2[k * NCLASS + j] : 0.0f);
    }
}

__global__ void cvt_x_kernel(const float* __restrict__ x) {
    size_t i = (size_t)blockIdx.x * blockDim.x + threadIdx.x;   // over NN*NFEAT/8
    if (i >= (size_t)NN * NFEAT / 8) return;
    const float4* p = (const float4*)x + i * 2;
    float4 a = p[0], b = p[1];
    uint4 u = make_uint4(h2u(__floats2half2_rn(a.x, a.y)), h2u(__floats2half2_rn(a.z, a.w)),
                         h2u(__floats2half2_rn(b.x, b.y)), h2u(__floats2half2_rn(b.z, b.w)));
    ((uint4*)g_xh)[i] = u;
}

// ---------------- CSR build ----------------
__global__ void hist_kernel(const int* __restrict__ dst) {
    int e = blockIdx.x * blockDim.x + threadIdx.x;
    if (e < EE) atomicAdd(&g_cnt[dst[e]], 1);
}

__global__ __launch_bounds__(1024) void scan_kernel() {
    __shared__ int sums[1024];
    const int T = 1024;
    const int IT = (NN + T - 1) / T;
    int t = threadIdx.x;
    int base = t * IT;
    int s = 0;
    for (int i = 0; i < IT; i++) {
        int idx = base + i;
        if (idx < NN) s += g_cnt[idx];
    }
    sums[t] = s;
    __syncthreads();
    for (int off = 1; off < T; off <<= 1) {
        int v = (t >= off) ? sums[t - off] : 0;
        __syncthreads();
        sums[t] += v;
        __syncthreads();
    }
    int run = sums[t] - s;
    for (int i = 0; i < IT; i++) {
        int idx = base + i;
        if (idx < NN) {
            g_rowptr[idx] = run;
            g_cursor[idx] = run;
            run += g_cnt[idx];
        }
    }
    if (t == T - 1) g_rowptr[NN] = sums[T - 1];
}

__global__ void scatter_kernel(const int* __restrict__ src,
                               const int* __restrict__ dst,
                               const float* __restrict__ w) {
    int e = blockIdx.x * blockDim.x + threadIdx.x;
    if (e < EE) {
        int d = dst[e];
        int p = atomicAdd(&g_cursor[d], 1);
        g_esrc[p] = src[e];
        g_ew[p]   = w[e];
    }
}

// =========================================================================
// GEMM1 (fp16 HMMA, cp.async double-buffered): g_support1h = fp16(x @ W1)
// M=NP, K=512, N=256. BM=128, BN=128, BK=32, 8 warps (2x4), warp 64x32.
// =========================================================================
__global__ __launch_bounds__(256) void gemm1_tc() {
    __shared__ __half As[2][128][40];
    __shared__ __half Bs[2][32][136];
    const int t   = threadIdx.x;
    const int wid = t >> 5;
    const int wr  = wid >> 2;     // 0..1
    const int wc  = wid & 3;      // 0..3
    const int row0 = blockIdx.y * 128;
    const int col0 = blockIdx.x * 128;

    wmma::fragment<wmma::accumulator, 16, 16, 16, float> acc[4][2];
#pragma unroll
    for (int i = 0; i < 4; i++)
#pragma unroll
        for (int j = 0; j < 2; j++) wmma::fill_fragment(acc[i][j], 0.0f);

    const int arow = t >> 1;          // 0..127
    const int ac16 = (t & 1) * 16;    // 0/16
    const int brow = t >> 3;          // 0..31
    const int bc16 = (t & 7) * 16;    // 0..112
    int garow = row0 + arow; if (garow >= NN) garow = NN - 1;
    const __half* Ap = g_xh + (size_t)garow * NFEAT;
    const __half* Bp = g_w1h + col0 + bc16;

    const int NIT = NFEAT / 32;   // 16
    cp_async16(&As[0][arow][ac16],     Ap + ac16);
    cp_async16(&As[0][arow][ac16 + 8], Ap + ac16 + 8);
    cp_async16(&Bs[0][brow][bc16],     Bp + (size_t)brow * NHID);
    cp_async16(&Bs[0][brow][bc16 + 8], Bp + (size_t)brow * NHID + 8);
    cp_commit();

    for (int i = 0; i < NIT; i++) {
        if (i + 1 < NIT) {
            int k1 = (i + 1) * 32;
            int nb = (i + 1) & 1;
            cp_async16(&As[nb][arow][ac16],     Ap + k1 + ac16);
            cp_async16(&As[nb][arow][ac16 + 8], Ap + k1 + ac16 + 8);
            cp_async16(&Bs[nb][brow][bc16],     Bp + (size_t)(k1 + brow) * NHID);
            cp_async16(&Bs[nb][brow][bc16 + 8], Bp + (size_t)(k1 + brow) * NHID + 8);
            cp_commit();
            cp_wait1();
        } else {
            cp_wait0();
        }
        __syncthreads();
        int cb = i & 1;
#pragma unroll
        for (int kk = 0; kk < 32; kk += 16) {
            wmma::fragment<wmma::matrix_a, 16, 16, 16, __half, wmma::row_major> af[4];
            wmma::fragment<wmma::matrix_b, 16, 16, 16, __half, wmma::row_major> bf[2];
#pragma unroll
            for (int ii = 0; ii < 4; ii++)
                wmma::load_matrix_sync(af[ii], &As[cb][wr * 64 + ii * 16][kk], 40);
#pragma unroll
            for (int j = 0; j < 2; j++)
                wmma::load_matrix_sync(bf[j], &Bs[cb][kk][wc * 32 + j * 16], 136);
#pragma unroll
            for (int ii = 0; ii < 4; ii++)
#pragma unroll
                for (int j = 0; j < 2; j++)
                    wmma::mma_sync(acc[ii][j], af[ii], bf[j], acc[ii][j]);
        }
        __syncthreads();
    }

    float* stage = (float*)&As[0][0][0] + wid * 320;
    const int L = t & 31;
    const int rr = L >> 1;
    const int cc = (L & 1) * 8;
#pragma unroll
    for (int i = 0; i < 4; i++)
#pragma unroll
        for (int j = 0; j < 2; j++) {
            wmma::store_matrix_sync(stage, acc[i][j], 20, wmma::mem_row_major);
            __syncwarp();
            const float* sp = stage + rr * 20 + cc;
            __half2 h0 = __floats2half2_rn(sp[0], sp[1]);
            __half2 h1 = __floats2half2_rn(sp[2], sp[3]);
            __half2 h2 = __floats2half2_rn(sp[4], sp[5]);
            __half2 h3 = __floats2half2_rn(sp[6], sp[7]);
            int gr = row0 + wr * 64 + i * 16 + rr;
            int gc = col0 + wc * 32 + j * 16 + cc;
            *(uint4*)(g_support1h + (size_t)gr * NHID + gc) =
                make_uint4(h2u(h0), h2u(h1), h2u(h2), h2u(h3));
            __syncwarp();
        }
}

// =========================================================================
// zdec fused: phase1 tmp = h1 @ [Wmu|Wlv] (regs);
// phase z: z = (mu+bmu) + eps*exp(lv+blv) via smem exchange (fp16 tile);
// phase2: x1 = relu(z @ Wdec + bdec) -> g_x1h.
// =========================================================================
__global__ __launch_bounds__(256) void zdec_tc(const float* __restrict__ bmu,
                                               const float* __restrict__ blv,
                                               const float* __restrict__ eps,
                                               const float* __restrict__ bdec) {
    extern __shared__ char arena[];
    __half (*hA)[128][40]  = (__half (*)[128][40])arena;            // 20480 B
    __half (*hB)[32][136]  = (__half (*)[32][136])(arena + 20480);  // 17408 B
    float*  lv_s  = (float*)arena;                   // [128][68]  34816 B
    __half* z_s   = (__half*)(arena + 34816);        // [128][72]  18432 B
    float*  stg   = (float*)(arena + 53248);         // 8 * 320 floats
    __half* bB    = (__half*)arena;                  // [64][136]  17408 B (phase2)

    const int t   = threadIdx.x;
    const int wid = t >> 5;
    const int wr  = wid >> 2;     // 0..1
    const int wc  = wid & 3;      // 0..3
    const int row0 = blockIdx.x * 128;
    const int L  = t & 31;
    const int rr = L >> 1;
    const int cc = (L & 1) * 8;

    wmma::fragment<wmma::accumulator, 16, 16, 16, float> acc[4][2];
#pragma unroll
    for (int i = 0; i < 4; i++)
#pragma unroll
        for (int j = 0; j < 2; j++) wmma::fill_fragment(acc[i][j], 0.0f);

    // ---- phase 1: tmp = h1 @ [Wmu|Wlv], K=256, N=128 ----
    {
        const int arow = t >> 1;
        const int ac16 = (t & 1) * 16;
        const int brow = t >> 3;
        const int bc16 = (t & 7) * 16;
        int garow = row0 + arow; if (garow >= NN) garow = NN - 1;
        const __half* Ap = g_h1h + (size_t)garow * NHID;
        const __half* Bp = g_wmlh + bc16;

        const int NIT = NHID / 32;   // 8
        cp_async16(&hA[0][arow][ac16],     Ap + ac16);
        cp_async16(&hA[0][arow][ac16 + 8], Ap + ac16 + 8);
        cp_async16(&hB[0][brow][bc16],     Bp + (size_t)brow * 128);
        cp_async16(&hB[0][brow][bc16 + 8], Bp + (size_t)brow * 128 + 8);
        cp_commit();

        for (int i = 0; i < NIT; i++) {
            if (i + 1 < NIT) {
                int k1 = (i + 1) * 32;
                int nb = (i + 1) & 1;
                cp_async16(&hA[nb][arow][ac16],     Ap + k1 + ac16);
                cp_async16(&hA[nb][arow][ac16 + 8], Ap + k1 + ac16 + 8);
                cp_async16(&hB[nb][brow][bc16],     Bp + (size_t)(k1 + brow) * 128);
                cp_async16(&hB[nb][brow][bc16 + 8], Bp + (size_t)(k1 + brow) * 128 + 8);
                cp_commit();
                cp_wait1();
            } else {
                cp_wait0();
            }
            __syncthreads();
            int cb = i & 1;
#pragma unroll
            for (int kk = 0; kk < 32; kk += 16) {
                wmma::fragment<wmma::matrix_a, 16, 16, 16, __half, wmma::row_major> af[4];
                wmma::fragment<wmma::matrix_b, 16, 16, 16, __half, wmma::row_major> bf[2];
#pragma unroll
                for (int ii = 0; ii < 4; ii++)
                    wmma::load_matrix_sync(af[ii], &hA[cb][wr * 64 + ii * 16][kk], 40);
#pragma unroll
                for (int j = 0; j < 2; j++)
                    wmma::load_matrix_sync(bf[j], &hB[cb][kk][wc * 32 + j * 16], 136);
#pragma unroll
                for (int ii = 0; ii < 4; ii++)
#pragma unroll
                    for (int j = 0; j < 2; j++)
                        wmma::mma_sync(acc[ii][j], af[ii], bf[j], acc[ii][j]);
            }
            __syncthreads();
        }
    }

    // ---- phase z ----
    if (wc >= 2) {
#pragma unroll
        for (int i = 0; i < 4; i++)
#pragma unroll
            for (int j = 0; j < 2; j++)
                wmma::store_matrix_sync(lv_s + (wr * 64 + i * 16) * 68 + (wc - 2) * 32 + j * 16,
                                        acc[i][j], 68, wmma::mem_row_major);
    }
    __syncthreads();
    if (wc < 2) {
        float* stage = stg + wid * 320;
#pragma unroll
        for (int i = 0; i < 4; i++)
#pragma unroll
            for (int j = 0; j < 2; j++) {
                wmma::store_matrix_sync(stage, acc[i][j], 20, wmma::mem_row_major);
                __syncwarp();
                const float* sp = stage + rr * 20 + cc;
                int row = wr * 64 + i * 16 + rr;
                int col = wc * 32 + j * 16 + cc;
                int ge = row0 + row; if (ge >= NN) ge = NN - 1;
                float4 e0 = *(const float4*)(eps + (size_t)ge * NCODE + col);
                float4 e1 = *(const float4*)(eps + (size_t)ge * NCODE + col + 4);
                float4 l0 = *(const float4*)(lv_s + row * 68 + col);
                float4 l1 = *(const float4*)(lv_s + row * 68 + col + 4);
                float4 bm0 = *(const float4*)(bmu + col);
                float4 bm1 = *(const float4*)(bmu + col + 4);
                float4 bl0 = *(const float4*)(blv + col);
                float4 bl1 = *(const float4*)(blv + col + 4);
                float z0 = (sp[0] + bm0.x) + e0.x * expf(l0.x + bl0.x);
                float z1 = (sp[1] + bm0.y) + e0.y * expf(l0.y + bl0.y);
                float z2 = (sp[2] + bm0.z) + e0.z * expf(l0.z + bl0.z);
                float z3 = (sp[3] + bm0.w) + e0.w * expf(l0.w + bl0.w);
                float z4 = (sp[4] + bm1.x) + e1.x * expf(l1.x + bl1.x);
                float z5 = (sp[5] + bm1.y) + e1.y * expf(l1.y + bl1.y);
                float z6 = (sp[6] + bm1.z) + e1.z * expf(l1.z + bl1.z);
                float z7 = (sp[7] + bm1.w) + e1.w * expf(l1.w + bl1.w);
                *(uint4*)(z_s + row * 72 + col) =
                    make_uint4(h2u(__floats2half2_rn(z0, z1)), h2u(__floats2half2_rn(z2, z3)),
                               h2u(__floats2half2_rn(z4, z5)), h2u(__floats2half2_rn(z6, z7)));
                __syncwarp();
            }
    }
    __syncthreads();

    // ---- phase 2: x1 = relu(z @ Wdec + bdec), K=64, N=256 in two halves ----
    for (int col0 = 0; col0 < NHID; col0 += 128) {
        {
            const __half* wp = g_wdech + (size_t)(t >> 2) * NHID + col0 + (t & 3) * 32;
            __half* bp = bB + (t >> 2) * 136 + (t & 3) * 32;
            *(uint4*)(bp)      = *(const uint4*)(wp);
            *(uint4*)(bp + 8)  = *(const uint4*)(wp + 8);
            *(uint4*)(bp + 16) = *(const uint4*)(wp + 16);
            *(uint4*)(bp + 24) = *(const uint4*)(wp + 24);
        }
        __syncthreads();

        wmma::fragment<wmma::accumulator, 16, 16, 16, float> acc2[4][2];
#pragma unroll
        for (int i = 0; i < 4; i++)
#pragma unroll
            for (int j = 0; j < 2; j++) wmma::fill_fragment(acc2[i][j], 0.0f);

#pragma unroll
        for (int kk = 0; kk < NCODE; kk += 16) {
            wmma::fragment<wmma::matrix_a, 16, 16, 16, __half, wmma::row_major> af[4];
            wmma::fragment<wmma::matrix_b, 16, 16, 16, __half, wmma::row_major> bf[2];
#pragma unroll
            for (int i = 0; i < 4; i++)
                wmma::load_matrix_sync(af[i], z_s + (wr * 64 + i * 16) * 72 + kk, 72);
#pragma unroll
            for (int j = 0; j < 2; j++)
                wmma::load_matrix_sync(bf[j], bB + kk * 136 + wc * 32 + j * 16, 136);
#pragma unroll
            for (int i = 0; i < 4; i++)
#pragma unroll
                for (int j = 0; j < 2; j++)
                    wmma::mma_sync(acc2[i][j], af[i], bf[j], acc2[i][j]);
        }

        float* stage = stg + wid * 320;
#pragma unroll
        for (int i = 0; i < 4; i++)
#pragma unroll
            for (int j = 0; j < 2; j++) {
                wmma::store_matrix_sync(stage, acc2[i][j], 20, wmma::mem_row_major);
                __syncwarp();
                const float* sp = stage + rr * 20 + cc;
                int gr = row0 + wr * 64 + i * 16 + rr;
                int gc = col0 + wc * 32 + j * 16 + cc;
                float4 bd0 = *(const float4*)(bdec + gc);
                float4 bd1 = *(const float4*)(bdec + gc + 4);
                float v0 = fmaxf(sp[0] + bd0.x, 0.f), v1 = fmaxf(sp[1] + bd0.y, 0.f);
                float v2 = fmaxf(sp[2] + bd0.z, 0.f), v3 = fmaxf(sp[3] + bd0.w, 0.f);
                float v4 = fmaxf(sp[4] + bd1.x, 0.f), v5 = fmaxf(sp[5] + bd1.y, 0.f);
                float v6 = fmaxf(sp[6] + bd1.z, 0.f), v7 = fmaxf(sp[7] + bd1.w, 0.f);
                *(uint4*)(g_x1h + (size_t)gr * NHID + gc) =
                    make_uint4(h2u(__floats2half2_rn(v0, v1)), h2u(__floats2half2_rn(v2, v3)),
                               h2u(__floats2half2_rn(v4, v5)), h2u(__floats2half2_rn(v6, v7)));
                __syncwarp();
            }
        __syncthreads();
    }
}

// =========================================================================
// out gemm (fp16 HMMA, cp.async double-buffered): g_support2h = [x1;h1] @ W2
// M=NP, K=512, N=64 (pre-padded). fp16 output via smem staging.
// =========================================================================
__global__ __launch_bounds__(256) void out_tc() {
    __shared__ __half As[2][128][40];
    __shared__ __half Bs[2][32][72];
    const int t   = threadIdx.x;
    const int wid = t >> 5;
    const int wr  = wid >> 1;     // 0..3
    const int wc  = wid & 1;      // 0..1
    const int row0 = blockIdx.x * 128;

    wmma::fragment<wmma::accumulator, 16, 16, 16, float> acc[2][2];
#pragma unroll
    for (int i = 0; i < 2; i++)
#pragma unroll
        for (int j = 0; j < 2; j++) wmma::fill_fragment(acc[i][j], 0.0f);

    const int arow = t >> 1;
    const int ac16 = (t & 1) * 16;
    const int brow = t >> 3;          // 0..31
    const int bc8  = (t & 7) * 8;     // 0..56
    int garow = row0 + arow; if (garow >= NN) garow = NN - 1;
    const __half* Ap1 = g_x1h + (size_t)garow * NHID;
    const __half* Ap2 = g_h1h + (size_t)garow * NHID;

    const int NIT = 2 * NHID / 32;   // 16
    {
        const __half* ap = Ap1 + ac16;
        cp_async16(&As[0][arow][ac16],     ap);
        cp_async16(&As[0][arow][ac16 + 8], ap + 8);
        cp_async16(&Bs[0][brow][bc8], g_w2h + (size_t)brow * 64 + bc8);
    }
    cp_commit();

    for (int i = 0; i < NIT; i++) {
        if (i + 1 < NIT) {
            int k1 = (i + 1) * 32;
            int nb = (i + 1) & 1;
            const __half* ap = (k1 < NHID) ? (Ap1 + k1 + ac16)
                                           : (Ap2 + (k1 - NHID) + ac16);
            cp_async16(&As[nb][arow][ac16],     ap);
            cp_async16(&As[nb][arow][ac16 + 8], ap + 8);
            cp_async16(&Bs[nb][brow][bc8], g_w2h + (size_t)(k1 + brow) * 64 + bc8);
            cp_commit();
            cp_wait1();
        } else {
            cp_wait0();
        }
        __syncthreads();
        int cb = i & 1;
#pragma unroll
        for (int kk = 0; kk < 32; kk += 16) {
            wmma::fragment<wmma::matrix_a, 16, 16, 16, __half, wmma::row_major> af[2];
            wmma::fragment<wmma::matrix_b, 16, 16, 16, __half, wmma::row_major> bf[2];
#pragma unroll
            for (int ii = 0; ii < 2; ii++)
                wmma::load_matrix_sync(af[ii], &As[cb][wr * 32 + ii * 16][kk], 40);
#pragma unroll
            for (int j = 0; j < 2; j++)
                wmma::load_matrix_sync(bf[j], &Bs[cb][kk][wc * 32 + j * 16], 72);
#pragma unroll
            for (int ii = 0; ii < 2; ii++)
#pragma unroll
                for (int j = 0; j < 2; j++)
                    wmma::mma_sync(acc[ii][j], af[ii], bf[j], acc[ii][j]);
        }
        __syncthreads();
    }

    // fp16 epilogue via staging (reuse As)
    float* stage = (float*)&As[0][0][0] + wid * 320;
    const int L = t & 31;
    const int rr = L >> 1;
    const int cc = (L & 1) * 8;
#pragma unroll
    for (int i = 0; i < 2; i++)
#pragma unroll
        for (int j = 0; j < 2; j++) {
            wmma::store_matrix_sync(stage, acc[i][j], 20, wmma::mem_row_major);
            __syncwarp();
            const float* sp = stage + rr * 20 + cc;
            int r = row0 + wr * 32 + i * 16 + rr;
            int c = wc * 32 + j * 16 + cc;
            *(uint4*)(g_support2h + (size_t)r * 64 + c) =
                make_uint4(h2u(__floats2half2_rn(sp[0], sp[1])),
                           h2u(__floats2half2_rn(sp[2], sp[3])),
                           h2u(__floats2half2_rn(sp[4], sp[5])),
                           h2u(__floats2half2_rn(sp[6], sp[7])));
            __syncwarp();
        }
}

// ---------------- spmm1 + bias + relu (fp16 gather, 8x unrolled) ---------
__global__ void spmm_relu_kernel(const float* __restrict__ b1) {
    int warp = (blockIdx.x * blockDim.x + threadIdx.x) >> 5;
    int lane = threadIdx.x & 31;
    if (warp >= NN) return;
    int beg = g_rowptr[warp];
    int end = g_rowptr[warp + 1];
    float acc[8] = {0, 0, 0, 0, 0, 0, 0, 0};
    const int co = lane * 8;
    int e = beg;
    for (; e + 8 <= end; e += 8) {
        uint4 u[8];
        float w[8];
#pragma unroll
        for (int k = 0; k < 8; k++) {
            int s = g_esrc[e + k];
            w[k] = g_ew[e + k];
            u[k] = *(const uint4*)(g_support1h + (size_t)s * NHID + co);
        }
#pragma unroll
        for (int k = 0; k < 8; k++) {
            __half2* h = (__half2*)&u[k];
#pragma unroll
            for (int q = 0; q < 4; q++) {
                float2 f = __half22float2(h[q]);
                acc[2 * q]     += w[k] * f.x;
                acc[2 * q + 1] += w[k] * f.y;
            }
        }
    }
    for (; e < end; e++) {
        int s = g_esrc[e];
        float w = g_ew[e];
        uint4 u = *(const uint4*)(g_support1h + (size_t)s * NHID + co);
        __half2* h = (__half2*)&u;
#pragma unroll
        for (int q = 0; q < 4; q++) {
            float2 f = __half22float2(h[q]);
            acc[2 * q]     += w * f.x;
            acc[2 * q + 1] += w * f.y;
        }
    }
    float4 bb0 = *(const float4*)(b1 + co);
    float4 bb1 = *(const float4*)(b1 + co + 4);
    float o[8];
    o[0] = fmaxf(acc[0] + bb0.x, 0.f); o[1] = fmaxf(acc[1] + bb0.y, 0.f);
    o[2] = fmaxf(acc[2] + bb0.z, 0.f); o[3] = fmaxf(acc[3] + bb0.w, 0.f);
    o[4] = fmaxf(acc[4] + bb1.x, 0.f); o[5] = fmaxf(acc[5] + bb1.y, 0.f);
    o[6] = fmaxf(acc[6] + bb1.z, 0.f); o[7] = fmaxf(acc[7] + bb1.w, 0.f);
    uint4 u = make_uint4(h2u(__floats2half2_rn(o[0], o[1])),
                         h2u(__floats2half2_rn(o[2], o[3])),
                         h2u(__floats2half2_rn(o[4], o[5])),
                         h2u(__floats2half2_rn(o[6], o[7])));
    *(uint4*)(g_h1h + (size_t)warp * NHID + co) = u;
}

// ---------------- spmm2 (fp16 gather, 4x unrolled) + log_softmax ---------
__global__ void spmm_softmax_kernel(const float* __restrict__ b2,
                                    float* __restrict__ out) {
    int warp = (blockIdx.x * blockDim.x + threadIdx.x) >> 5;
    int lane = threadIdx.x & 31;
    if (warp >= NN) return;
    int beg = g_rowptr[warp];
    int end = g_rowptr[warp + 1];
    bool active = lane < 10;                   // 10 lanes x 4 cols = 40
    float acc[4] = {0, 0, 0, 0};
    int e = beg;
    for (; e + 4 <= end; e += 4) {
        if (active) {
            uint2 u[4];
            float w[4];
#pragma unroll
            for (int k = 0; k < 4; k++) {
                int s = g_esrc[e + k];
                w[k] = g_ew[e + k];
                u[k] = *(const uint2*)(g_support2h + (size_t)s * 64 + lane * 4);
            }
#pragma unroll
            for (int k = 0; k < 4; k++) {
                __half2* hp = (__half2*)&u[k];
                float2 f0 = __half22float2(hp[0]);
                float2 f1 = __half22float2(hp[1]);
                acc[0] += w[k] * f0.x; acc[1] += w[k] * f0.y;
                acc[2] += w[k] * f1.x; acc[3] += w[k] * f1.y;
            }
        }
    }
    for (; e < end; e++) {
        int s = g_esrc[e];
        float w = g_ew[e];
        if (active) {
            uint2 u = *(const uint2*)(g_support2h + (size_t)s * 64 + lane * 4);
            __half2* hp = (__half2*)&u;
            float2 f0 = __half22float2(hp[0]);
            float2 f1 = __half22float2(hp[1]);
            acc[0] += w * f0.x; acc[1] += w * f0.y;
            acc[2] += w * f1.x; acc[3] += w * f1.y;
        }
    }
    float4 v = make_float4(-INFINITY, -INFINITY, -INFINITY, -INFINITY);
    if (active) {
        float4 b = *(const float4*)(b2 + lane * 4);
        v.x = acc[0] + b.x; v.y = acc[1] + b.y; v.z = acc[2] + b.z; v.w = acc[3] + b.w;
    }
    float m = fmaxf(fmaxf(v.x, v.y), fmaxf(v.z, v.w));
#pragma unroll
    for (int off = 16; off > 0; off >>= 1)
        m = fmaxf(m, __shfl_xor_sync(0xFFFFFFFFu, m, off));
    float s = active ? (expf(v.x - m) + expf(v.y - m) + expf(v.z - m) + expf(v.w - m)) : 0.0f;
#pragma unroll
    for (int off = 16; off > 0; off >>= 1)
        s += __shfl_xor_sync(0xFFFFFFFFu, s, off);
    float lse = m + logf(s);
    if (active) {
        float4 o;
        o.x = v.x - lse; o.y = v.y - lse; o.z = v.z - lse; o.w = v.w - lse;
        ((float4*)(out + (size_t)warp * NCLASS))[lane] = o;
    }
}

// ---------------- launch ----------------
extern "C" void kernel_launch(void* const* d_in, const int* in_sizes, int n_in,
                              void* d_out, int out_size) {
    const float* x        = (const float*)d_in[0];
    const int*   edge_src = (const int*)  d_in[1];
    const int*   edge_dst = (const int*)  d_in[2];
    const float* edge_w   = (const float*)d_in[3];
    const float* eps      = (const float*)d_in[4];
    const float* W1       = (const float*)d_in[5];
    const float* b1       = (const float*)d_in[6];
    const float* W_mu     = (const float*)d_in[7];
    const float* b_mu     = (const float*)d_in[8];
    const float* W_lv     = (const float*)d_in[9];
    const float* b_lv     = (const float*)d_in[10];
    const float* W_dec    = (const float*)d_in[11];
    const float* b_dec    = (const float*)d_in[12];
    const float* W2       = (const float*)d_in[13];
    const float* b2       = (const float*)d_in[14];
    float* out = (float*)d_out;

    static cudaStream_t s2 = nullptr;
    static cudaEvent_t ev_fork = nullptr, ev_join = nullptr;
    static bool init_done = false;
    if (!init_done) {
        cudaFuncSetAttribute(zdec_tc, cudaFuncAttributeMaxDynamicSharedMemorySize, 65536);
        cudaStreamCreateWithFlags(&s2, cudaStreamNonBlocking);
        cudaEventCreateWithFlags(&ev_fork, cudaEventDisableTiming);
        cudaEventCreateWithFlags(&ev_join, cudaEventDisableTiming);
        init_done = true;
    }

    void* cnt_ptr = nullptr;
    cudaGetSymbolAddress(&cnt_ptr, g_cnt);

    // fork: CSR chain on s2, concurrent with cvt + gemm1 on the main stream
    cudaEventRecord(ev_fork, 0);
    cudaStreamWaitEvent(s2, ev_fork, 0);

    cudaMemsetAsync(cnt_ptr, 0, NN * sizeof(int), s2);
    hist_kernel<<<(EE + 255) / 256, 256, 0, s2>>>(edge_dst);
    scan_kernel<<<1, 1024, 0, s2>>>();
    scatter_kernel<<<(EE + 255) / 256, 256, 0, s2>>>(edge_src, edge_dst, edge_w);
    cudaEventRecord(ev_join, s2);

    cvt_w_kernel<<<(NFEAT * NHID + 255) / 256, 256>>>(W1, W_mu, W_lv, W_dec, W2);
    cvt_x_kernel<<<((size_t)NN * NFEAT / 8 + 255) / 256, 256>>>(x);
    gemm1_tc<<<dim3(NHID / 128, NP / 128), 256>>>();

    // join CSR
    cudaStreamWaitEvent(0, ev_join, 0);

    // h1(fp16) = relu(spmm + b1)
    spmm_relu_kernel<<<(NN * 32 + 255) / 256, 256>>>(b1);

    // fused: tmp -> z -> x1
    zdec_tc<<<NP / 128, 256, 65536>>>(b_mu, b_lv, eps, b_dec);

    // support2(fp16) = [x1; h1] @ W2
    out_tc<<<NP / 128, 256>>>();

    // out = log_softmax(spmm + b2)
    spmm_softmax_kernel<<<(NN * 32 + 255) / 256, 256>>>(b2, out);
}